// round 2
// baseline (speedup 1.0000x reference)
#include <cuda_runtime.h>
#include <cuda_bf16.h>
#include <cstdint>

// Problem constants: q,k,v : (4, 8, 64, 8192) fp32  -> 32 heads of (64, 8192)
#define HEADS   32
#define D       64
#define S       8192
#define CHUNKS  16
#define CHUNK_S (S / CHUNKS)   // 512
#define SUB     64             // s-subtile held in smem per iteration (kernel B)
#define BSTRIDE 68             // padded row stride (floats) for kernel-B tiles
#define STILE   128            // s-tile for kernel C
#define CSTRIDE 68             // padded row stride for transposed ctx in kernel C

// Scratch (device globals; no allocation allowed)
__device__ float g_part_ctx[HEADS * CHUNKS * D * D];   // 8 MiB
__device__ float g_part_rsum[HEADS * CHUNKS * D];
__device__ float g_ctx[HEADS * D * D];                 // normalized, scale folded in

// ---------------------------------------------------------------------------
// Kernel B: per (head, chunk) compute partial context
//   part_ctx[i][j] = sum_{s in chunk} exp(k[i,s]) * v[j,s]
//   part_rsum[i]   = sum_{s in chunk} exp(k[i,s])
// ---------------------------------------------------------------------------
__global__ void __launch_bounds__(256) kernelB(const float* __restrict__ K,
                                               const float* __restrict__ V) {
    __shared__ float sK[D * BSTRIDE];
    __shared__ float sV[D * BSTRIDE];

    const int h  = blockIdx.y;
    const int ch = blockIdx.x;
    const float* Kh = K + (size_t)h * D * S + (size_t)ch * CHUNK_S;
    const float* Vh = V + (size_t)h * D * S + (size_t)ch * CHUNK_S;

    const int tid = threadIdx.x;
    const int tx = tid & 15;   // j-group
    const int ty = tid >> 4;   // i-group / load row group

    float acc[4][4] = {};
    float rs[4] = {0.f, 0.f, 0.f, 0.f};

    for (int sb = 0; sb < CHUNK_S; sb += SUB) {
        __syncthreads();
        // Load subtile: rows ty+16t, float4 column tx. exp applied to K.
        #pragma unroll
        for (int t = 0; t < 4; t++) {
            const int row = ty + 16 * t;
            float4 kv = *(const float4*)(Kh + (size_t)row * S + sb + tx * 4);
            float4 e;
            e.x = __expf(kv.x); e.y = __expf(kv.y);
            e.z = __expf(kv.z); e.w = __expf(kv.w);
            *(float4*)&sK[row * BSTRIDE + tx * 4] = e;
            rs[t] += e.x + e.y + e.z + e.w;
            float4 vv = *(const float4*)(Vh + (size_t)row * S + sb + tx * 4);
            *(float4*)&sV[row * BSTRIDE + tx * 4] = vv;
        }
        __syncthreads();

        // Outer-product accumulation: i = ty+16m, j = tx+16n
        #pragma unroll 4
        for (int ss = 0; ss < SUB; ss += 4) {
            float4 a[4], b[4];
            #pragma unroll
            for (int m = 0; m < 4; m++)
                a[m] = *(const float4*)&sK[(ty + 16 * m) * BSTRIDE + ss];
            #pragma unroll
            for (int n = 0; n < 4; n++)
                b[n] = *(const float4*)&sV[(tx + 16 * n) * BSTRIDE + ss];
            #pragma unroll
            for (int m = 0; m < 4; m++) {
                #pragma unroll
                for (int n = 0; n < 4; n++) {
                    acc[m][n] += a[m].x * b[n].x;
                    acc[m][n] += a[m].y * b[n].y;
                    acc[m][n] += a[m].z * b[n].z;
                    acc[m][n] += a[m].w * b[n].w;
                }
            }
        }
    }

    // Reduce row sums: row (ty + 16t) is spread over the 16 threads sharing ty
    // (contiguous 16 lanes). xor-shuffle over bits 0..3 stays inside the group.
    #pragma unroll
    for (int t = 0; t < 4; t++) {
        float v = rs[t];
        v += __shfl_xor_sync(0xFFFFFFFFu, v, 8);
        v += __shfl_xor_sync(0xFFFFFFFFu, v, 4);
        v += __shfl_xor_sync(0xFFFFFFFFu, v, 2);
        v += __shfl_xor_sync(0xFFFFFFFFu, v, 1);
        if (tx == 0)
            g_part_rsum[(h * CHUNKS + ch) * D + ty + 16 * t] = v;
    }

    // Store partial context
    float* pc = g_part_ctx + (size_t)(h * CHUNKS + ch) * D * D;
    #pragma unroll
    for (int m = 0; m < 4; m++) {
        const int i = ty + 16 * m;
        #pragma unroll
        for (int n = 0; n < 4; n++) {
            const int j = tx + 16 * n;
            pc[i * D + j] = acc[m][n];
        }
    }
}

// ---------------------------------------------------------------------------
// Kernel B2: reduce partials, normalize rows by row-sum, fold in d^-0.5 scale
// ---------------------------------------------------------------------------
__global__ void __launch_bounds__(256) kernelB2() {
    const int h = blockIdx.x;
    const int tid = threadIdx.x;
    __shared__ float sinv[D];
    if (tid < D) {
        float s = 0.f;
        #pragma unroll
        for (int c = 0; c < CHUNKS; c++)
            s += g_part_rsum[(h * CHUNKS + c) * D + tid];
        sinv[tid] = 0.125f / s;   // scale = 64^-0.5 = 0.125 folded here
    }
    __syncthreads();
    for (int idx = tid; idx < D * D; idx += 256) {
        float s = 0.f;
        #pragma unroll
        for (int c = 0; c < CHUNKS; c++)
            s += g_part_ctx[(size_t)(h * CHUNKS + c) * D * D + idx];
        g_ctx[h * D * D + idx] = s * sinv[idx >> 6];
    }
}

// ---------------------------------------------------------------------------
// Kernel C: per (head, s-tile of 128):
//   eq = exp(q tile); colsum over d; out[j,s] = (1/colsum[s]) * sum_i ctx[i,j]*eq[i,s]
// ---------------------------------------------------------------------------
__global__ void __launch_bounds__(256) kernelC(const float* __restrict__ Q,
                                               float* __restrict__ O) {
    extern __shared__ float sm[];
    float* sq      = sm;                      // 64 * 128
    float* sctxT   = sm + D * STILE;          // 64 * CSTRIDE  (ctx transposed: [j][i])
    float* scolinv = sctxT + D * CSTRIDE;     // 128

    const int h  = blockIdx.y;
    const int sb = blockIdx.x * STILE;
    const int tid = threadIdx.x;

    // Load ctx transposed into smem
    const float* ctxh = g_ctx + h * D * D;
    for (int idx = tid; idx < D * D; idx += 256) {
        const int i = idx >> 6, j = idx & 63;
        sctxT[j * CSTRIDE + i] = ctxh[idx];
    }

    // Load q tile with exp-on-load
    const float* Qh = Q + (size_t)h * D * S + sb;
    #pragma unroll
    for (int t = 0; t < 8; t++) {
        const int idx = tid + (t << 8);
        const int row = idx >> 5, c4 = idx & 31;
        float4 v = *(const float4*)(Qh + (size_t)row * S + c4 * 4);
        float4 e;
        e.x = __expf(v.x); e.y = __expf(v.y);
        e.z = __expf(v.z); e.w = __expf(v.w);
        *(float4*)&sq[row * STILE + c4 * 4] = e;
    }
    __syncthreads();

    // Column softmax denominators (warp reads 32 consecutive columns per i)
    if (tid < STILE) {
        float s = 0.f;
        #pragma unroll 8
        for (int i = 0; i < D; i++) s += sq[i * STILE + tid];
        scolinv[tid] = 1.0f / s;
    }
    __syncthreads();

    // GEMM: out[j][s] with j = jg+16m (m=0..3), s = sg*8 + p (p=0..7)
    const int sg = tid & 15;
    const int jg = tid >> 4;
    float acc[4][8] = {};

    for (int i0 = 0; i0 < D; i0 += 4) {
        float4 cm[4];
        #pragma unroll
        for (int m = 0; m < 4; m++)
            cm[m] = *(const float4*)&sctxT[(jg + 16 * m) * CSTRIDE + i0];
        #pragma unroll
        for (int ii = 0; ii < 4; ii++) {
            float4 qa = *(const float4*)&sq[(i0 + ii) * STILE + sg * 8];
            float4 qb = *(const float4*)&sq[(i0 + ii) * STILE + sg * 8 + 4];
            #pragma unroll
            for (int m = 0; m < 4; m++) {
                const float c = ((const float*)&cm[m])[ii];
                acc[m][0] += c * qa.x; acc[m][1] += c * qa.y;
                acc[m][2] += c * qa.z; acc[m][3] += c * qa.w;
                acc[m][4] += c * qb.x; acc[m][5] += c * qb.y;
                acc[m][6] += c * qb.z; acc[m][7] += c * qb.w;
            }
        }
    }

    float inv[8];
    #pragma unroll
    for (int p = 0; p < 8; p++) inv[p] = scolinv[sg * 8 + p];

    #pragma unroll
    for (int m = 0; m < 4; m++) {
        const int j = jg + 16 * m;
        float* op = O + ((size_t)h * D + j) * S + sb + sg * 8;
        float4 o0, o1;
        o0.x = acc[m][0] * inv[0]; o0.y = acc[m][1] * inv[1];
        o0.z = acc[m][2] * inv[2]; o0.w = acc[m][3] * inv[3];
        o1.x = acc[m][4] * inv[4]; o1.y = acc[m][5] * inv[5];
        o1.z = acc[m][6] * inv[6]; o1.w = acc[m][7] * inv[7];
        *(float4*)op = o0;
        *(float4*)(op + 4) = o1;
    }
}

// ---------------------------------------------------------------------------
extern "C" void kernel_launch(void* const* d_in, const int* in_sizes, int n_in,
                              void* d_out, int out_size) {
    const float* q = (const float*)d_in[0];
    const float* k = (const float*)d_in[1];
    const float* v = (const float*)d_in[2];
    float* o = (float*)d_out;

    static const int smemC = (D * STILE + D * CSTRIDE + STILE) * (int)sizeof(float);
    cudaFuncSetAttribute(kernelC, cudaFuncAttributeMaxDynamicSharedMemorySize, smemC);

    dim3 gridB(CHUNKS, HEADS);
    kernelB<<<gridB, 256>>>(k, v);
    kernelB2<<<HEADS, 256>>>();
    dim3 gridC(S / STILE, HEADS);
    kernelC<<<gridC, 256, smemC>>>(q, o);
}

// round 4
// speedup vs baseline: 1.3447x; 1.3447x over previous
#include <cuda_runtime.h>
#include <cuda_bf16.h>
#include <cstdint>

#define HEADS 32
#define D 64
#define S 8192

#define CHUNKS 16
#define CH_S (S / CHUNKS)   // 512
#define SUBS 64             // s-subtile per smem iteration (kernel B)
#define C_ST 128            // s-tile kernel C

// ---------------- scratch ----------------
__device__ __align__(16) float g_part_ctx[HEADS * CHUNKS * D * D];   // 8 MiB
__device__ __align__(16) float g_part_rsum[HEADS * CHUNKS * D];
__device__ __align__(16) __nv_bfloat16 g_ctxT_hi[HEADS * D * D];     // [h][j][i]
__device__ __align__(16) __nv_bfloat16 g_ctxT_lo[HEADS * D * D];

// ---------------- helpers ----------------
__device__ __forceinline__ uint32_t smem_u32(const void* p) {
    uint32_t a;
    asm("{ .reg .u64 t; cvta.to.shared.u64 t, %1; cvt.u32.u64 %0, t; }" : "=r"(a) : "l"(p));
    return a;
}
// SW128 swizzle on tile-relative byte offsets (tiles are 1024B-aligned)
#define SW(o) ((uint32_t)(o) ^ ((((uint32_t)(o)) >> 3) & 0x70))

__device__ __forceinline__ void ldmx4(uint32_t* r, uint32_t addr) {
    asm volatile("ldmatrix.sync.aligned.m8n8.x4.shared.b16 {%0,%1,%2,%3}, [%4];"
                 : "=r"(r[0]), "=r"(r[1]), "=r"(r[2]), "=r"(r[3]) : "r"(addr));
}
__device__ __forceinline__ void ldmx4t(uint32_t* r, uint32_t addr) {
    asm volatile("ldmatrix.sync.aligned.m8n8.x4.trans.shared.b16 {%0,%1,%2,%3}, [%4];"
                 : "=r"(r[0]), "=r"(r[1]), "=r"(r[2]), "=r"(r[3]) : "r"(addr));
}
__device__ __forceinline__ void mma16816(float* c, const uint32_t* a,
                                         uint32_t b0, uint32_t b1) {
    asm volatile(
        "mma.sync.aligned.m16n8k16.row.col.f32.bf16.bf16.f32 "
        "{%0,%1,%2,%3}, {%4,%5,%6,%7}, {%8,%9}, {%0,%1,%2,%3};"
        : "+f"(c[0]), "+f"(c[1]), "+f"(c[2]), "+f"(c[3])
        : "r"(a[0]), "r"(a[1]), "r"(a[2]), "r"(a[3]), "r"(b0), "r"(b1));
}
// pack (x -> low half, y -> high half)
__device__ __forceinline__ uint32_t bf2(float x, float y) {
    uint32_t d;
    asm("cvt.rn.bf16x2.f32 %0, %1, %2;" : "=r"(d) : "f"(y), "f"(x));
    return d;
}
// split 4 floats into hi/lo bf16x2 pairs (consecutive elements per u32)
__device__ __forceinline__ void split4(float a, float b, float c, float d,
                                       uint2& hi, uint2& lo) {
    hi.x = bf2(a, b);
    hi.y = bf2(c, d);
    float ra = a - __uint_as_float(hi.x << 16);
    float rb = b - __uint_as_float(hi.x & 0xFFFF0000u);
    float rc = c - __uint_as_float(hi.y << 16);
    float rd = d - __uint_as_float(hi.y & 0xFFFF0000u);
    lo.x = bf2(ra, rb);
    lo.y = bf2(rc, rd);
}
__device__ __forceinline__ uint16_t bfu(float x) {
    __nv_bfloat16 h = __float2bfloat16_rn(x);
    return *(uint16_t*)&h;
}
__device__ __forceinline__ float bff(uint16_t u) {
    __nv_bfloat16 h = *(__nv_bfloat16*)&u;
    return __bfloat162float(h);
}

// =====================================================================
// Kernel B: per (head, chunk=512s): part_ctx[i][j] = sum_s eK[i,s] V[j,s]
// smem tiles (64 x 64 bf16, 128B rows, SW128): Kh@0 Kl@8K Vh@16K Vl@24K
// =====================================================================
__global__ void __launch_bounds__(256) kernelB(const float* __restrict__ K,
                                               const float* __restrict__ V) {
    __shared__ __align__(1024) char sm[32768 + 256];
    const uint32_t sb = smem_u32(sm);
    float* sRS = (float*)(sm + 32768);
    const int tid = threadIdx.x, lane = tid & 31, wid = tid >> 5;
    const int ch = blockIdx.x, h = blockIdx.y;

    if (tid < 64) sRS[tid] = 0.f;
    __syncthreads();

    const size_t gbase = (size_t)h * D * S + (size_t)ch * CH_S;
    const int wm = wid & 3, wn = wid >> 2;
    const int lr = (lane & 7) + ((lane >> 3) & 1) * 8;  // ldmatrix row
    const int lcs = lane >> 4;                          // ldmatrix 16B col-seg

    float acc[4][4] = {};

    for (int sbk = 0; sbk < CH_S; sbk += SUBS) {
        __syncthreads();
        #pragma unroll
        for (int u = 0; u < 4; u++) {
            const int idx = tid + (u << 8);     // 0..1023 float4
            const int r = idx >> 4, c4 = idx & 15;
            const size_t g = gbase + (size_t)r * S + sbk + c4 * 4;
            float4 kv = *(const float4*)(K + g);
            float4 vv = *(const float4*)(V + g);
            float e0 = __expf(kv.x), e1 = __expf(kv.y);
            float e2 = __expf(kv.z), e3 = __expf(kv.w);
            float rsum = e0 + e1 + e2 + e3;
            rsum += __shfl_xor_sync(~0u, rsum, 1);
            rsum += __shfl_xor_sync(~0u, rsum, 2);
            rsum += __shfl_xor_sync(~0u, rsum, 4);
            rsum += __shfl_xor_sync(~0u, rsum, 8);
            if ((lane & 15) == 0) atomicAdd(&sRS[r], rsum);
            const uint32_t so = SW(r * 128 + c4 * 8);
            uint2 hi, lo;
            split4(e0, e1, e2, e3, hi, lo);
            *(uint2*)(sm + so) = hi;
            *(uint2*)(sm + 8192 + so) = lo;
            split4(vv.x, vv.y, vv.z, vv.w, hi, lo);
            *(uint2*)(sm + 16384 + so) = hi;
            *(uint2*)(sm + 24576 + so) = lo;
        }
        __syncthreads();

        #pragma unroll
        for (int ks = 0; ks < 4; ks++) {
            const uint32_t aoff = SW((16 * wm + lr) * 128 + ks * 32 + lcs * 16);
            uint32_t ah[4], al[4];
            ldmx4(ah, sb + aoff);
            ldmx4(al, sb + 8192 + aoff);
            uint32_t bh[2][4], bl[2][4];
            #pragma unroll
            for (int hlf = 0; hlf < 2; hlf++) {
                const uint32_t boff =
                    SW((32 * wn + 16 * hlf + lr) * 128 + ks * 32 + lcs * 16);
                ldmx4(bh[hlf], sb + 16384 + boff);
                ldmx4(bl[hlf], sb + 24576 + boff);
            }
            #pragma unroll
            for (int nt = 0; nt < 4; nt++) {
                const int hf = nt >> 1, sub = nt & 1;
                const uint32_t bh0 = bh[hf][sub], bh1 = bh[hf][sub + 2];
                const uint32_t bl0 = bl[hf][sub], bl1 = bl[hf][sub + 2];
                mma16816(acc[nt], ah, bh0, bh1);
                mma16816(acc[nt], ah, bl0, bl1);
                mma16816(acc[nt], al, bh0, bh1);
            }
        }
    }

    if (tid < 64) g_part_rsum[(h * CHUNKS + ch) * D + tid] = sRS[tid];

    float* pc = g_part_ctx + (size_t)(h * CHUNKS + ch) * (D * D);
    const int g8 = lane >> 2, tig = lane & 3;
    #pragma unroll
    for (int nt = 0; nt < 4; nt++) {
        const int j = 32 * wn + 8 * nt + 2 * tig;
        const int i0 = 16 * wm + g8;
        float2 v0 = {acc[nt][0], acc[nt][1]};
        float2 v1 = {acc[nt][2], acc[nt][3]};
        *(float2*)&pc[i0 * D + j] = v0;
        *(float2*)&pc[(i0 + 8) * D + j] = v1;
    }
}

// =====================================================================
// Kernel B2: reduce chunk partials, normalize rows, fold 1/8 scale,
// write transposed hi/lo bf16 ctx^T[j][i]
// =====================================================================
__global__ void __launch_bounds__(256) kernelB2() {
    const int h = blockIdx.x, tid = threadIdx.x;
    __shared__ float sinv[D];
    if (tid < D) {
        float s = 0.f;
        #pragma unroll
        for (int c = 0; c < CHUNKS; c++) s += g_part_rsum[(h * CHUNKS + c) * D + tid];
        sinv[tid] = 0.125f / s;
    }
    __syncthreads();
    for (int idx = tid; idx < D * D; idx += 256) {
        const int i = idx >> 6, j = idx & 63;
        float s = 0.f;
        #pragma unroll
        for (int c = 0; c < CHUNKS; c++)
            s += g_part_ctx[(size_t)(h * CHUNKS + c) * (D * D) + idx];
        const float val = s * sinv[i];
        const uint16_t hi = bfu(val);
        const uint16_t lo = bfu(val - bff(hi));
        g_ctxT_hi[h * D * D + j * D + i] = *(__nv_bfloat16*)&hi;
        g_ctxT_lo[h * D * D + j * D + i] = *(__nv_bfloat16*)&lo;
    }
}

// =====================================================================
// Kernel C: per (head, s-tile=128): out[j,s] = colinv[s]*sum_i ctxT[j,i]*EQ[i,s]
// A = ctxT (K-major, non-trans ldmatrix); B = EQ stored [i][s] (MN-major,
// trans ldmatrix) -> no staging transpose. smem:
//  ctxTh@0 ctxTl@8K | EQh: 2 s-half tiles @16K,+8K | EQl @32K,+8K | colsum@48K
// =====================================================================
#define C_COLS 49152
__global__ void __launch_bounds__(256) kernelC(const float* __restrict__ Q,
                                               float* __restrict__ O) {
    extern __shared__ __align__(1024) char sm[];
    const uint32_t sb = smem_u32(sm);
    float* colsum = (float*)(sm + C_COLS);
    const int tid = threadIdx.x, lane = tid & 31, wid = tid >> 5;
    const int st = blockIdx.x, h = blockIdx.y;

    if (tid < 128) colsum[tid] = 0.f;
    __syncthreads();

    // ctx^T tiles (64 x 64 bf16, swizzled copy)
    {
        const uint64_t* srcH = (const uint64_t*)(g_ctxT_hi + h * D * D);
        const uint64_t* srcL = (const uint64_t*)(g_ctxT_lo + h * D * D);
        #pragma unroll
        for (int u = 0; u < 4; u++) {
            const int idx = tid + (u << 8);      // 0..1023 8B units
            const uint32_t so = SW(idx * 8);
            *(uint64_t*)(sm + so) = srcH[idx];
            *(uint64_t*)(sm + 8192 + so) = srcL[idx];
        }
    }

    // EQ tiles: load Q [i][s], exp on load, accumulate colsums
    const size_t qbase = (size_t)h * D * S + (size_t)st * C_ST;
    const int s4 = tid & 31, iw = tid >> 5;
    float cs0 = 0.f, cs1 = 0.f, cs2 = 0.f, cs3 = 0.f;
    const int tsel = s4 >> 4;                    // s-half tile
    const int srel = (s4 & 15) * 4;              // s within half
    #pragma unroll
    for (int u = 0; u < 8; u++) {
        const int i = iw + 8 * u;
        float4 qv = *(const float4*)(Q + qbase + (size_t)i * S + s4 * 4);
        float e0 = __expf(qv.x), e1 = __expf(qv.y);
        float e2 = __expf(qv.z), e3 = __expf(qv.w);
        cs0 += e0; cs1 += e1; cs2 += e2; cs3 += e3;
        uint2 hi, lo;
        split4(e0, e1, e2, e3, hi, lo);
        const uint32_t so = SW(i * 128 + srel * 2);
        *(uint2*)(sm + 16384 + tsel * 8192 + so) = hi;
        *(uint2*)(sm + 32768 + tsel * 8192 + so) = lo;
    }
    atomicAdd(&colsum[s4 * 4 + 0], cs0);
    atomicAdd(&colsum[s4 * 4 + 1], cs1);
    atomicAdd(&colsum[s4 * 4 + 2], cs2);
    atomicAdd(&colsum[s4 * 4 + 3], cs3);
    __syncthreads();
    if (tid < 128) colsum[tid] = 1.0f / colsum[tid];
    __syncthreads();

    // MMA: warp tile j=16*(wid&3), s-half 64*(wid>>2)
    const int wm = wid & 3, wn = wid >> 2;
    const int lr = (lane & 7) + ((lane >> 3) & 1) * 8;
    const int lcs = lane >> 4;
    float acc[8][4] = {};

    #pragma unroll
    for (int ks = 0; ks < 4; ks++) {
        const uint32_t aoff = SW((16 * wm + lr) * 128 + ks * 32 + lcs * 16);
        uint32_t ah[4], al[4];
        ldmx4(ah, sb + aoff);
        ldmx4(al, sb + 8192 + aoff);
        #pragma unroll
        for (int nb = 0; nb < 4; nb++) {         // n16 blocks within 64 s
            const uint32_t boff = SW((ks * 16 + lr) * 128 + (nb * 16 + lcs * 8) * 2);
            uint32_t bh[4], bl[4];
            ldmx4t(bh, sb + 16384 + wn * 8192 + boff);
            ldmx4t(bl, sb + 32768 + wn * 8192 + boff);
            float* a0 = acc[2 * nb];
            float* a1 = acc[2 * nb + 1];
            mma16816(a0, ah, bh[0], bh[1]);
            mma16816(a0, ah, bl[0], bl[1]);
            mma16816(a0, al, bh[0], bh[1]);
            mma16816(a1, ah, bh[2], bh[3]);
            mma16816(a1, ah, bl[2], bl[3]);
            mma16816(a1, al, bh[2], bh[3]);
        }
    }

    // epilogue: scale by colinv, store
    const int g8 = lane >> 2, tig = lane & 3;
    #pragma unroll
    for (int nt = 0; nt < 8; nt++) {
        const int sl = wn * 64 + nt * 8 + 2 * tig;
        const float2 inv = *(const float2*)&colsum[sl];
        const int j = 16 * wm + g8;
        const size_t ob = ((size_t)h * D + j) * S + (size_t)st * C_ST + sl;
        float2 v0 = {acc[nt][0] * inv.x, acc[nt][1] * inv.y};
        float2 v1 = {acc[nt][2] * inv.x, acc[nt][3] * inv.y};
        *(float2*)(O + ob) = v0;
        *(float2*)(O + ob + 8 * S) = v1;
    }
}

// =====================================================================
extern "C" void kernel_launch(void* const* d_in, const int* in_sizes, int n_in,
                              void* d_out, int out_size) {
    const float* q = (const float*)d_in[0];
    const float* k = (const float*)d_in[1];
    const float* v = (const float*)d_in[2];
    float* o = (float*)d_out;

    const int smemC = C_COLS + 512;   // 49664 B
    cudaFuncSetAttribute(kernelC, cudaFuncAttributeMaxDynamicSharedMemorySize, smemC);

    dim3 gridB(CHUNKS, HEADS);
    kernelB<<<gridB, 256>>>(k, v);
    kernelB2<<<HEADS, 256>>>();
    dim3 gridC(S / C_ST, HEADS);
    kernelC<<<gridC, 256, smemC>>>(q, o);
}

// round 5
// speedup vs baseline: 1.8372x; 1.3662x over previous
#include <cuda_runtime.h>
#include <cuda_bf16.h>
#include <cstdint>

#define HEADS 32
#define D 64
#define S 8192

#define CHUNKS 16
#define CH_S (S / CHUNKS)   // 512
#define SUBS 64             // s-subtile per smem iteration (kernel B)
#define B_NIT (CH_S / SUBS) // 8
#define C_ST 128            // s-tile kernel C
#define C_TPC 2             // s-tiles per CTA in kernel C

// ---------------- scratch ----------------
__device__ __align__(16) float g_part_ctx[HEADS * CHUNKS * D * D];   // 8 MiB
__device__ __align__(16) float g_part_rsum[HEADS * CHUNKS * D];
__device__ __align__(16) __nv_bfloat16 g_ctxT_hi[HEADS * D * D];     // [h][j][i]
__device__ __align__(16) __nv_bfloat16 g_ctxT_lo[HEADS * D * D];

// ---------------- helpers ----------------
__device__ __forceinline__ uint32_t smem_u32(const void* p) {
    uint32_t a;
    asm("{ .reg .u64 t; cvta.to.shared.u64 t, %1; cvt.u32.u64 %0, t; }" : "=r"(a) : "l"(p));
    return a;
}
#define SW(o) ((uint32_t)(o) ^ ((((uint32_t)(o)) >> 3) & 0x70))

__device__ __forceinline__ void ldmx4(uint32_t* r, uint32_t addr) {
    asm volatile("ldmatrix.sync.aligned.m8n8.x4.shared.b16 {%0,%1,%2,%3}, [%4];"
                 : "=r"(r[0]), "=r"(r[1]), "=r"(r[2]), "=r"(r[3]) : "r"(addr));
}
__device__ __forceinline__ void ldmx4t(uint32_t* r, uint32_t addr) {
    asm volatile("ldmatrix.sync.aligned.m8n8.x4.trans.shared.b16 {%0,%1,%2,%3}, [%4];"
                 : "=r"(r[0]), "=r"(r[1]), "=r"(r[2]), "=r"(r[3]) : "r"(addr));
}
__device__ __forceinline__ void mma16816(float* c, const uint32_t* a,
                                         uint32_t b0, uint32_t b1) {
    asm volatile(
        "mma.sync.aligned.m16n8k16.row.col.f32.bf16.bf16.f32 "
        "{%0,%1,%2,%3}, {%4,%5,%6,%7}, {%8,%9}, {%0,%1,%2,%3};"
        : "+f"(c[0]), "+f"(c[1]), "+f"(c[2]), "+f"(c[3])
        : "r"(a[0]), "r"(a[1]), "r"(a[2]), "r"(a[3]), "r"(b0), "r"(b1));
}
__device__ __forceinline__ uint32_t bf2(float x, float y) {
    uint32_t d;
    asm("cvt.rn.bf16x2.f32 %0, %1, %2;" : "=r"(d) : "f"(y), "f"(x));
    return d;
}
__device__ __forceinline__ void split4(float a, float b, float c, float d,
                                       uint2& hi, uint2& lo) {
    hi.x = bf2(a, b);
    hi.y = bf2(c, d);
    float ra = a - __uint_as_float(hi.x << 16);
    float rb = b - __uint_as_float(hi.x & 0xFFFF0000u);
    float rc = c - __uint_as_float(hi.y << 16);
    float rd = d - __uint_as_float(hi.y & 0xFFFF0000u);
    lo.x = bf2(ra, rb);
    lo.y = bf2(rc, rd);
}
__device__ __forceinline__ uint16_t bfu(float x) {
    __nv_bfloat16 h = __float2bfloat16_rn(x);
    return *(uint16_t*)&h;
}
__device__ __forceinline__ float bff(uint16_t u) {
    __nv_bfloat16 h = *(__nv_bfloat16*)&u;
    return __bfloat162float(h);
}

// =====================================================================
// Kernel B: per (head, chunk=512s): part_ctx[i][j] = sum_s eK[i,s] V[j,s]
// smem tiles (64 x 64 bf16, 128B rows, SW128): Kh@0 Kl@8K Vh@16K Vl@24K
// Register-prefetch pipeline: loads for subtile t+1 overlap MMA on tile t.
// =====================================================================
__global__ void __launch_bounds__(256, 2) kernelB(const float* __restrict__ K,
                                                  const float* __restrict__ V) {
    __shared__ __align__(1024) char sm[32768 + 256];
    const uint32_t sb = smem_u32(sm);
    float* sRS = (float*)(sm + 32768);
    const int tid = threadIdx.x, lane = tid & 31, wid = tid >> 5;
    const int ch = blockIdx.x, h = blockIdx.y;

    if (tid < 64) sRS[tid] = 0.f;

    const size_t gbase = (size_t)h * D * S + (size_t)ch * CH_S;
    const int wm = wid & 3, wn = wid >> 2;
    const int lr = (lane & 7) + ((lane >> 3) & 1) * 8;  // ldmatrix row
    const int lcs = lane >> 4;                          // ldmatrix 16B col-seg

    // fixed per-thread load geometry (4 float4 per tensor per subtile)
    const float* kp[4];
    const float* vp[4];
    uint32_t so_[4];
    int rrow[4];
    #pragma unroll
    for (int u = 0; u < 4; u++) {
        const int idx = tid + (u << 8);
        const int r = idx >> 4, c4 = idx & 15;
        rrow[u] = r;
        so_[u] = SW(r * 128 + c4 * 8);
        kp[u] = K + gbase + (size_t)r * S + c4 * 4;
        vp[u] = V + gbase + (size_t)r * S + c4 * 4;
    }

    float4 pk[4], pv[4];
    #pragma unroll
    for (int u = 0; u < 4; u++) { pk[u] = *(const float4*)kp[u]; pv[u] = *(const float4*)vp[u]; }

    float acc[4][4] = {};

    for (int t = 0; t < B_NIT; t++) {
        __syncthreads();   // previous MMA done reading smem (also covers sRS init)
        #pragma unroll
        for (int u = 0; u < 4; u++) {
            float e0 = __expf(pk[u].x), e1 = __expf(pk[u].y);
            float e2 = __expf(pk[u].z), e3 = __expf(pk[u].w);
            float rsum = e0 + e1 + e2 + e3;
            rsum += __shfl_xor_sync(~0u, rsum, 1);
            rsum += __shfl_xor_sync(~0u, rsum, 2);
            rsum += __shfl_xor_sync(~0u, rsum, 4);
            rsum += __shfl_xor_sync(~0u, rsum, 8);
            if ((lane & 15) == 0) atomicAdd(&sRS[rrow[u]], rsum);
            uint2 hi, lo;
            split4(e0, e1, e2, e3, hi, lo);
            *(uint2*)(sm + so_[u]) = hi;
            *(uint2*)(sm + 8192 + so_[u]) = lo;
            split4(pv[u].x, pv[u].y, pv[u].z, pv[u].w, hi, lo);
            *(uint2*)(sm + 16384 + so_[u]) = hi;
            *(uint2*)(sm + 24576 + so_[u]) = lo;
        }
        __syncthreads();

        if (t + 1 < B_NIT) {
            const int off = (t + 1) * SUBS;
            #pragma unroll
            for (int u = 0; u < 4; u++) {
                pk[u] = *(const float4*)(kp[u] + off);
                pv[u] = *(const float4*)(vp[u] + off);
            }
        }

        #pragma unroll
        for (int ks = 0; ks < 4; ks++) {
            const uint32_t aoff = SW((16 * wm + lr) * 128 + ks * 32 + lcs * 16);
            uint32_t ah[4], al[4];
            ldmx4(ah, sb + aoff);
            ldmx4(al, sb + 8192 + aoff);
            uint32_t bh[2][4], bl[2][4];
            #pragma unroll
            for (int hlf = 0; hlf < 2; hlf++) {
                const uint32_t boff =
                    SW((32 * wn + 16 * hlf + lr) * 128 + ks * 32 + lcs * 16);
                ldmx4(bh[hlf], sb + 16384 + boff);
                ldmx4(bl[hlf], sb + 24576 + boff);
            }
            #pragma unroll
            for (int nt = 0; nt < 4; nt++) {
                const int hf = nt >> 1, sub = nt & 1;
                const uint32_t bh0 = bh[hf][sub], bh1 = bh[hf][sub + 2];
                const uint32_t bl0 = bl[hf][sub], bl1 = bl[hf][sub + 2];
                mma16816(acc[nt], ah, bh0, bh1);
                mma16816(acc[nt], ah, bl0, bl1);
                mma16816(acc[nt], al, bh0, bh1);
            }
        }
    }
    __syncthreads();

    if (tid < 64) g_part_rsum[(h * CHUNKS + ch) * D + tid] = sRS[tid];

    float* pc = g_part_ctx + (size_t)(h * CHUNKS + ch) * (D * D);
    const int g8 = lane >> 2, tig = lane & 3;
    #pragma unroll
    for (int nt = 0; nt < 4; nt++) {
        const int j = 32 * wn + 8 * nt + 2 * tig;
        const int i0 = 16 * wm + g8;
        float2 v0 = {acc[nt][0], acc[nt][1]};
        float2 v1 = {acc[nt][2], acc[nt][3]};
        *(float2*)&pc[i0 * D + j] = v0;
        *(float2*)&pc[(i0 + 8) * D + j] = v1;
    }
}

// =====================================================================
// Kernel B2: reduce chunk partials, normalize rows, fold 1/8 scale,
// write transposed hi/lo bf16 ctx^T[j][i]
// =====================================================================
__global__ void __launch_bounds__(256) kernelB2() {
    const int h = blockIdx.x, tid = threadIdx.x;
    __shared__ float sinv[D];
    if (tid < D) {
        float s = 0.f;
        #pragma unroll
        for (int c = 0; c < CHUNKS; c++) s += g_part_rsum[(h * CHUNKS + c) * D + tid];
        sinv[tid] = 0.125f / s;
    }
    __syncthreads();
    for (int idx = tid; idx < D * D; idx += 256) {
        const int i = idx >> 6, j = idx & 63;
        float s = 0.f;
        #pragma unroll
        for (int c = 0; c < CHUNKS; c++)
            s += g_part_ctx[(size_t)(h * CHUNKS + c) * (D * D) + idx];
        const float val = s * sinv[i];
        const uint16_t hi = bfu(val);
        const uint16_t lo = bfu(val - bff(hi));
        g_ctxT_hi[h * D * D + j * D + i] = *(__nv_bfloat16*)&hi;
        g_ctxT_lo[h * D * D + j * D + i] = *(__nv_bfloat16*)&lo;
    }
}

// =====================================================================
// Kernel C: per (head, pair of s-tiles): out[j,s] = colinv[s]*sum_i ctxT[j,i]*EQ[i,s]
// Two tiles per CTA, register-prefetch pipeline. smem:
//  ctxTh@0 ctxTl@8K | EQh @16K (2x8K halves) | EQl @32K | colsum[2][128] @48K
// =====================================================================
#define C_COLS 49152
__global__ void __launch_bounds__(256, 2) kernelC(const float* __restrict__ Q,
                                                  float* __restrict__ O) {
    extern __shared__ __align__(1024) char sm[];
    const uint32_t sb = smem_u32(sm);
    const int tid = threadIdx.x, lane = tid & 31, wid = tid >> 5;
    const int stp = blockIdx.x, h = blockIdx.y;

    if (tid < 256) {
        ((float*)(sm + C_COLS))[tid] = 0.f;   // both colsum buffers
    }

    // per-thread Q geometry: 8 float4 per tile
    const size_t qbase = (size_t)h * D * S + (size_t)stp * (C_TPC * C_ST);
    const int s4 = tid & 31, iw = tid >> 5;
    const int tsel = s4 >> 4;
    const int srel = (s4 & 15) * 4;
    const float* qp[8];
    #pragma unroll
    for (int u = 0; u < 8; u++)
        qp[u] = Q + qbase + (size_t)(iw + 8 * u) * S + s4 * 4;

    float4 pq[8];
    #pragma unroll
    for (int u = 0; u < 8; u++) pq[u] = *(const float4*)qp[u];

    // ctx^T tiles (64 x 64 bf16, swizzled copy) — overlaps Q loads in flight
    {
        const uint64_t* srcH = (const uint64_t*)(g_ctxT_hi + h * D * D);
        const uint64_t* srcL = (const uint64_t*)(g_ctxT_lo + h * D * D);
        #pragma unroll
        for (int u = 0; u < 4; u++) {
            const int idx = tid + (u << 8);
            const uint32_t so = SW(idx * 8);
            *(uint64_t*)(sm + so) = srcH[idx];
            *(uint64_t*)(sm + 8192 + so) = srcL[idx];
        }
    }

    const int wm = wid & 3, wn = wid >> 2;
    const int lr = (lane & 7) + ((lane >> 3) & 1) * 8;
    const int lcs = lane >> 4;
    const int g8 = lane >> 2, tig = lane & 3;

    for (int t = 0; t < C_TPC; t++) {
        __syncthreads();   // prev MMA done with EQ smem (and ctx/colsum ready at t=0)
        float* colsum = (float*)(sm + C_COLS) + t * 128;
        {
            float cs0 = 0.f, cs1 = 0.f, cs2 = 0.f, cs3 = 0.f;
            #pragma unroll
            for (int u = 0; u < 8; u++) {
                const int i = iw + 8 * u;
                float e0 = __expf(pq[u].x), e1 = __expf(pq[u].y);
                float e2 = __expf(pq[u].z), e3 = __expf(pq[u].w);
                cs0 += e0; cs1 += e1; cs2 += e2; cs3 += e3;
                uint2 hi, lo;
                split4(e0, e1, e2, e3, hi, lo);
                const uint32_t so = SW(i * 128 + srel * 2);
                *(uint2*)(sm + 16384 + tsel * 8192 + so) = hi;
                *(uint2*)(sm + 32768 + tsel * 8192 + so) = lo;
            }
            atomicAdd(&colsum[s4 * 4 + 0], cs0);
            atomicAdd(&colsum[s4 * 4 + 1], cs1);
            atomicAdd(&colsum[s4 * 4 + 2], cs2);
            atomicAdd(&colsum[s4 * 4 + 3], cs3);
        }
        __syncthreads();

        if (t + 1 < C_TPC) {
            #pragma unroll
            for (int u = 0; u < 8; u++)
                pq[u] = *(const float4*)(qp[u] + (t + 1) * C_ST);
        }

        float acc[8][4] = {};
        #pragma unroll
        for (int ks = 0; ks < 4; ks++) {
            const uint32_t aoff = SW((16 * wm + lr) * 128 + ks * 32 + lcs * 16);
            uint32_t ah[4], al[4];
            ldmx4(ah, sb + aoff);
            ldmx4(al, sb + 8192 + aoff);
            #pragma unroll
            for (int nb = 0; nb < 4; nb++) {
                const uint32_t boff = SW((ks * 16 + lr) * 128 + (nb * 16 + lcs * 8) * 2);
                uint32_t bh[4], bl[4];
                ldmx4t(bh, sb + 16384 + wn * 8192 + boff);
                ldmx4t(bl, sb + 32768 + wn * 8192 + boff);
                float* a0 = acc[2 * nb];
                float* a1 = acc[2 * nb + 1];
                mma16816(a0, ah, bh[0], bh[1]);
                mma16816(a0, ah, bl[0], bl[1]);
                mma16816(a0, al, bh[0], bh[1]);
                mma16816(a1, ah, bh[2], bh[3]);
                mma16816(a1, ah, bl[2], bl[3]);
                mma16816(a1, al, bh[2], bh[3]);
            }
        }

        // epilogue: scale by 1/colsum, store
        #pragma unroll
        for (int nt = 0; nt < 8; nt++) {
            const int sl = wn * 64 + nt * 8 + 2 * tig;
            const float2 cs = *(const float2*)&colsum[sl];
            const float ix = __frcp_rn(cs.x), iy = __frcp_rn(cs.y);
            const int j = 16 * wm + g8;
            const size_t ob = ((size_t)h * D + j) * S
                            + (size_t)stp * (C_TPC * C_ST) + (size_t)t * C_ST + sl;
            float2 v0 = {acc[nt][0] * ix, acc[nt][1] * iy};
            float2 v1 = {acc[nt][2] * ix, acc[nt][3] * iy};
            *(float2*)(O + ob) = v0;
            *(float2*)(O + ob + 8 * S) = v1;
        }
    }
}

// =====================================================================
extern "C" void kernel_launch(void* const* d_in, const int* in_sizes, int n_in,
                              void* d_out, int out_size) {
    const float* q = (const float*)d_in[0];
    const float* k = (const float*)d_in[1];
    const float* v = (const float*)d_in[2];
    float* o = (float*)d_out;

    const int smemC = C_COLS + 1024;   // 50176 B
    cudaFuncSetAttribute(kernelC, cudaFuncAttributeMaxDynamicSharedMemorySize, smemC);

    dim3 gridB(CHUNKS, HEADS);
    kernelB<<<gridB, 256>>>(k, v);
    kernelB2<<<HEADS, 256>>>();
    dim3 gridC(S / (C_TPC * C_ST), HEADS);
    kernelC<<<gridC, 256, smemC>>>(q, o);
}